// round 1
// baseline (speedup 1.0000x reference)
#include <cuda_runtime.h>

#define MAXN   10048
#define MAXCB  157
#define MAXP   1000

// ---- static device scratch (no allocations allowed) ----
__device__ unsigned long long g_mask[(size_t)MAXN * MAXCB];  // suppression bitmask rows
__device__ float4             g_sboxes[MAXN];                // boxes in sorted order
__device__ float              g_sscores[MAXN];               // scores in sorted order
__device__ int                g_rank[MAXN];                  // sorted position of input i
__device__ unsigned long long g_keep[MAXCB];                 // keep bits per 64-chunk
__device__ int                g_prefix[MAXCB];               // kept-count prefix per chunk

// ---------------------------------------------------------------------------
// K0: zero the rank accumulators (graph replays reuse the static buffer)
// ---------------------------------------------------------------------------
__global__ void k_zero(int n) {
    int i = blockIdx.x * blockDim.x + threadIdx.x;
    if (i < n) g_rank[i] = 0;
}

// ---------------------------------------------------------------------------
// K1: stable descending rank via brute-force counting.
// rank[i] = #{ j : s_j > s_i  ||  (s_j == s_i && j < i) }
// 2D grid: x over i-chunks, y over j-segments; partial counts via atomicAdd.
// ---------------------------------------------------------------------------
__global__ void k_count(const float* __restrict__ scores, int N, int segSize) {
    int i  = blockIdx.x * blockDim.x + threadIdx.x;
    int j0 = blockIdx.y * segSize;
    int j1 = min(j0 + segSize, N);
    __shared__ float sh[256];

    float si = (i < N) ? scores[i] : 0.0f;
    int cnt = 0;
    for (int jb = j0; jb < j1; jb += 256) {
        int j = jb + threadIdx.x;
        sh[threadIdx.x] = (j < j1) ? scores[j] : -1e30f;  // sentinel: never > , never ==
        __syncthreads();
        int lim = min(256, j1 - jb);
        #pragma unroll 4
        for (int t = 0; t < lim; t++) {
            float sj = sh[t];
            int jg = jb + t;
            cnt += (sj > si) || (sj == si && jg < i);
        }
        __syncthreads();
    }
    if (i < N && cnt) atomicAdd(&g_rank[i], cnt);
}

// ---------------------------------------------------------------------------
// K1b: scatter inputs into sorted order
// ---------------------------------------------------------------------------
__global__ void k_scatter(const float4* __restrict__ boxes,
                          const float* __restrict__ scores, int N) {
    int i = blockIdx.x * blockDim.x + threadIdx.x;
    if (i >= N) return;
    int r = g_rank[i];
    g_sboxes[r]  = boxes[i];
    g_sscores[r] = scores[i];
}

// ---------------------------------------------------------------------------
// K2: pairwise IoU suppression bitmask (upper triangle of 64x64 blocks).
// blockIdx.y = row block, blockIdx.x = col block (col >= row only).
// Thread t = row within row-block; 64 col boxes cached in shared.
// bit j set  <=>  col_global > row_global  &&  IoU > 0.5
// ---------------------------------------------------------------------------
__global__ void k_mask(int N, int CB) {
    int cb = blockIdx.x, rb = blockIdx.y;
    if (cb < rb) return;
    __shared__ float4 cbox[64];
    int t  = threadIdx.x;
    int cg = cb * 64 + t;
    cbox[t] = (cg < N) ? g_sboxes[cg] : make_float4(0.f, 0.f, 0.f, 0.f);
    __syncthreads();

    int rg = rb * 64 + t;
    if (rg >= N) return;
    float4 r = g_sboxes[rg];
    float ra = (r.z - r.x) * (r.w - r.y);

    unsigned long long m = 0;
    int lim = min(64, N - cb * 64);
    for (int j = 0; j < lim; j++) {
        int cgj = cb * 64 + j;
        if (cgj <= rg) continue;  // only suppress later (lower-score) boxes
        float4 c = cbox[j];
        float ix1 = fmaxf(r.x, c.x), iy1 = fmaxf(r.y, c.y);
        float ix2 = fminf(r.z, c.z), iy2 = fminf(r.w, c.w);
        float iw = fmaxf(ix2 - ix1, 0.0f), ih = fmaxf(iy2 - iy1, 0.0f);
        float inter = iw * ih;
        float ca = (c.z - c.x) * (c.w - c.y);
        float u  = fmaxf(ra + ca - inter, 1e-9f);
        if (inter > 0.5f * u) m |= 1ull << j;
    }
    g_mask[(size_t)rg * CB + cb] = m;
}

// ---------------------------------------------------------------------------
// K3: the serial greedy scan, chunked by 64.
// Phase A (thread 0): resolve diagonal chunk from shared-preloaded diag masks.
// Phase B (all threads): OR kept rows into removed[] for future chunks.
// Tail: prefix sums of kept counts for the MAX_PROPOSALS cutoff.
// ---------------------------------------------------------------------------
__global__ void k_scan(int N, int CB) {
    __shared__ unsigned long long removed[MAXCB];
    __shared__ unsigned long long diag[64];
    __shared__ unsigned long long keepw;
    int tid = threadIdx.x;

    for (int w = tid; w < CB; w += blockDim.x) removed[w] = 0ull;
    __syncthreads();

    for (int c = 0; c < CB; c++) {
        // preload diagonal block masks
        if (tid < 64) {
            int g = c * 64 + tid;
            diag[tid] = (g < N) ? g_mask[(size_t)g * CB + c] : 0ull;
        }
        __syncthreads();

        if (tid == 0) {
            unsigned long long rem = removed[c];
            unsigned long long kp  = 0ull;
            #pragma unroll
            for (int i = 0; i < 64; i++) {
                unsigned long long bit = 1ull << i;
                if (!(rem & bit)) { kp |= bit; rem |= diag[i]; }
            }
            int valid = N - c * 64;
            if (valid < 64) kp &= (valid <= 0) ? 0ull : ((1ull << valid) - 1ull);
            keepw = kp;
            removed[c] = rem;
            g_keep[c] = kp;
        }
        __syncthreads();

        unsigned long long kp = keepw;
        for (int w = c + 1 + tid; w < CB; w += blockDim.x) {
            unsigned long long acc = removed[w];
            unsigned long long k = kp;
            while (k) {
                int i = __ffsll((long long)k) - 1;
                k &= k - 1;
                acc |= g_mask[(size_t)(c * 64 + i) * CB + w];
            }
            removed[w] = acc;
        }
        __syncthreads();
    }

    if (tid == 0) {
        int run = 0;
        for (int c = 0; c < CB; c++) {
            g_prefix[c] = run;
            run += __popcll(g_keep[c]);
        }
    }
}

// ---------------------------------------------------------------------------
// K4: apply MAX_PROPOSALS cutoff and emit outputs:
//   out[0 : 4N)      boxes_out (sorted order, zeroed where not kept)
//   out[4N : 5N)     scores_out
//   out[5N : 6N)     keep flag as 0.0/1.0
// ---------------------------------------------------------------------------
__global__ void k_out(float* __restrict__ out, int N) {
    int p = blockIdx.x * blockDim.x + threadIdx.x;
    if (p >= N) return;
    int c = p >> 6, i = p & 63;
    unsigned long long kw = g_keep[c];
    bool kept = (kw >> i) & 1ull;
    int r = g_prefix[c] + __popcll(kw & ((1ull << i) - 1ull));
    bool fin = kept && (r < MAXP);

    float4 b = fin ? g_sboxes[p] : make_float4(0.f, 0.f, 0.f, 0.f);
    ((float4*)out)[p] = b;
    out[4 * N + p] = fin ? g_sscores[p] : 0.0f;
    out[5 * N + p] = fin ? 1.0f : 0.0f;
}

// ---------------------------------------------------------------------------
extern "C" void kernel_launch(void* const* d_in, const int* in_sizes, int n_in,
                              void* d_out, int out_size) {
    const float4* boxes  = (const float4*)d_in[0];
    const float*  scores = (const float*)d_in[1];
    int N  = in_sizes[1];
    int CB = (N + 63) / 64;

    k_zero<<<(N + 255) / 256, 256>>>(N);

    int segSize = (N + 7) / 8;
    dim3 g1((N + 255) / 256, 8);
    k_count<<<g1, 256>>>(scores, N, segSize);

    k_scatter<<<(N + 255) / 256, 256>>>(boxes, scores, N);

    dim3 g2(CB, CB);
    k_mask<<<g2, 64>>>(N, CB);

    k_scan<<<1, 256>>>(N, CB);

    k_out<<<(N + 255) / 256, 256>>>((float*)d_out, N);
}

// round 2
// speedup vs baseline: 2.2100x; 2.2100x over previous
#include <cuda_runtime.h>

#define MAXN   10048
#define MAXCB  157
#define MAXP   1000

// ---- static device scratch (no allocations allowed) ----
__device__ unsigned long long g_mask[(size_t)MAXN * MAXCB];  // suppression bitmask rows
__device__ float4             g_sboxes[MAXN];                // boxes in sorted order
__device__ float              g_sscores[MAXN];               // scores in sorted order
__device__ int                g_rank[MAXN];                  // sorted position of input i
__device__ unsigned long long g_keep[MAXCB];                 // keep bits per 64-chunk
__device__ int                g_prefix[MAXCB];               // kept-count prefix per chunk

// ---------------------------------------------------------------------------
// K0: zero the rank accumulators (graph replays reuse the static buffer)
// ---------------------------------------------------------------------------
__global__ void k_zero(int n) {
    int i = blockIdx.x * blockDim.x + threadIdx.x;
    if (i < n) g_rank[i] = 0;
}

// ---------------------------------------------------------------------------
// K1: stable descending rank via brute-force counting.
// rank[i] = #{ j : s_j > s_i  ||  (s_j == s_i && j < i) }
// ---------------------------------------------------------------------------
__global__ void k_count(const float* __restrict__ scores, int N, int segSize) {
    int i  = blockIdx.x * blockDim.x + threadIdx.x;
    int j0 = blockIdx.y * segSize;
    int j1 = min(j0 + segSize, N);
    __shared__ float sh[256];

    float si = (i < N) ? scores[i] : 0.0f;
    int cnt = 0;
    for (int jb = j0; jb < j1; jb += 256) {
        int j = jb + threadIdx.x;
        sh[threadIdx.x] = (j < j1) ? scores[j] : -1e30f;
        __syncthreads();
        int lim = min(256, j1 - jb);
        #pragma unroll 4
        for (int t = 0; t < lim; t++) {
            float sj = sh[t];
            int jg = jb + t;
            cnt += (sj > si) || (sj == si && jg < i);
        }
        __syncthreads();
    }
    if (i < N && cnt) atomicAdd(&g_rank[i], cnt);
}

// ---------------------------------------------------------------------------
// K1b: scatter inputs into sorted order
// ---------------------------------------------------------------------------
__global__ void k_scatter(const float4* __restrict__ boxes,
                          const float* __restrict__ scores, int N) {
    int i = blockIdx.x * blockDim.x + threadIdx.x;
    if (i >= N) return;
    int r = g_rank[i];
    g_sboxes[r]  = boxes[i];
    g_sscores[r] = scores[i];
}

// ---------------------------------------------------------------------------
// K2: pairwise IoU suppression bitmask (upper triangle of 64x64 blocks).
// ---------------------------------------------------------------------------
__global__ void k_mask(int N, int CB) {
    int cb = blockIdx.x, rb = blockIdx.y;
    if (cb < rb) return;
    __shared__ float4 cbox[64];
    int t  = threadIdx.x;
    int cg = cb * 64 + t;
    cbox[t] = (cg < N) ? g_sboxes[cg] : make_float4(0.f, 0.f, 0.f, 0.f);
    __syncthreads();

    int rg = rb * 64 + t;
    if (rg >= N) return;
    float4 r = g_sboxes[rg];
    float ra = (r.z - r.x) * (r.w - r.y);

    unsigned long long m = 0;
    int lim = min(64, N - cb * 64);
    for (int j = 0; j < lim; j++) {
        int cgj = cb * 64 + j;
        if (cgj <= rg) continue;  // only suppress later (lower-score) boxes
        float4 c = cbox[j];
        float ix1 = fmaxf(r.x, c.x), iy1 = fmaxf(r.y, c.y);
        float ix2 = fminf(r.z, c.z), iy2 = fminf(r.w, c.w);
        float iw = fmaxf(ix2 - ix1, 0.0f), ih = fmaxf(iy2 - iy1, 0.0f);
        float inter = iw * ih;
        float ca = (c.z - c.x) * (c.w - c.y);
        float u  = fmaxf(ra + ca - inter, 1e-9f);
        if (inter > 0.5f * u) m |= 1ull << j;
    }
    g_mask[(size_t)rg * CB + cb] = m;
}

// ---------------------------------------------------------------------------
// K3: serial greedy scan, chunked by 64.
// Phase A (thread 0): resolve diagonal chunk, extract kept indices -> klist.
// Phase B: one thread per future word w; unrolled INDEPENDENT loads over
// klist (MLP ~8, coalesced across threads).
// ---------------------------------------------------------------------------
__global__ void k_scan(int N, int CB) {
    __shared__ unsigned long long removed[MAXCB];
    __shared__ unsigned long long diag[64];
    __shared__ int klist[64];
    __shared__ int s_nk;
    int tid = threadIdx.x;

    for (int w = tid; w < CB; w += blockDim.x) removed[w] = 0ull;
    __syncthreads();

    for (int c = 0; c < CB; c++) {
        // preload diagonal block masks
        if (tid < 64) {
            int g = c * 64 + tid;
            diag[tid] = (g < N) ? g_mask[(size_t)g * CB + c] : 0ull;
        }
        __syncthreads();

        if (tid == 0) {
            unsigned long long rem = removed[c];
            unsigned long long kp  = 0ull;
            #pragma unroll
            for (int i = 0; i < 64; i++) {
                unsigned long long bit = 1ull << i;
                if (!(rem & bit)) { kp |= bit; rem |= diag[i]; }
            }
            int valid = N - c * 64;
            if (valid < 64) kp &= (valid <= 0) ? 0ull : ((1ull << valid) - 1ull);
            removed[c] = rem;
            g_keep[c] = kp;
            // extract kept indices for phase B
            int n = 0;
            unsigned long long k = kp;
            while (k) {
                int i = __ffsll((long long)k) - 1;
                k &= k - 1;
                klist[n++] = i;
            }
            s_nk = n;
        }
        __syncthreads();

        int w = c + 1 + tid;
        if (w < CB) {
            unsigned long long acc = removed[w];
            int n = s_nk;
            const unsigned long long* mp = g_mask + w;
            long long cbase = (long long)c * 64;
            int t = 0;
            for (; t + 8 <= n; t += 8) {
                unsigned long long a0 = mp[(cbase + klist[t + 0]) * CB];
                unsigned long long a1 = mp[(cbase + klist[t + 1]) * CB];
                unsigned long long a2 = mp[(cbase + klist[t + 2]) * CB];
                unsigned long long a3 = mp[(cbase + klist[t + 3]) * CB];
                unsigned long long a4 = mp[(cbase + klist[t + 4]) * CB];
                unsigned long long a5 = mp[(cbase + klist[t + 5]) * CB];
                unsigned long long a6 = mp[(cbase + klist[t + 6]) * CB];
                unsigned long long a7 = mp[(cbase + klist[t + 7]) * CB];
                acc |= a0 | a1 | a2 | a3 | a4 | a5 | a6 | a7;
            }
            for (; t < n; t++)
                acc |= mp[(cbase + klist[t]) * CB];
            removed[w] = acc;
        }
        __syncthreads();
    }

    if (tid == 0) {
        int run = 0;
        for (int c = 0; c < CB; c++) {
            g_prefix[c] = run;
            run += __popcll(g_keep[c]);
        }
    }
}

// ---------------------------------------------------------------------------
// K4: apply MAX_PROPOSALS cutoff and emit outputs:
//   out[0 : 4N) boxes | out[4N : 5N) scores | out[5N : 6N) keep as 0/1
// ---------------------------------------------------------------------------
__global__ void k_out(float* __restrict__ out, int N) {
    int p = blockIdx.x * blockDim.x + threadIdx.x;
    if (p >= N) return;
    int c = p >> 6, i = p & 63;
    unsigned long long kw = g_keep[c];
    bool kept = (kw >> i) & 1ull;
    int r = g_prefix[c] + __popcll(kw & ((1ull << i) - 1ull));
    bool fin = kept && (r < MAXP);

    float4 b = fin ? g_sboxes[p] : make_float4(0.f, 0.f, 0.f, 0.f);
    ((float4*)out)[p] = b;
    out[4 * N + p] = fin ? g_sscores[p] : 0.0f;
    out[5 * N + p] = fin ? 1.0f : 0.0f;
}

// ---------------------------------------------------------------------------
extern "C" void kernel_launch(void* const* d_in, const int* in_sizes, int n_in,
                              void* d_out, int out_size) {
    const float4* boxes  = (const float4*)d_in[0];
    const float*  scores = (const float*)d_in[1];
    int N  = in_sizes[1];
    int CB = (N + 63) / 64;

    k_zero<<<(N + 255) / 256, 256>>>(N);

    int segSize = (N + 7) / 8;
    dim3 g1((N + 255) / 256, 8);
    k_count<<<g1, 256>>>(scores, N, segSize);

    k_scatter<<<(N + 255) / 256, 256>>>(boxes, scores, N);

    dim3 g2(CB, CB);
    k_mask<<<g2, 64>>>(N, CB);

    k_scan<<<1, 256>>>(N, CB);

    k_out<<<(N + 255) / 256, 256>>>((float*)d_out, N);
}

// round 3
// speedup vs baseline: 7.5743x; 3.4273x over previous
#include <cuda_runtime.h>

#define MAXN   10048
#define MAXCB  157
#define MAXP   1000

// ---- static device scratch (no allocations allowed) ----
__device__ unsigned long long g_mask[(size_t)MAXN * MAXCB];  // suppression bitmask rows
__device__ unsigned long long g_diag[MAXN];                  // compact diagonal-block masks
__device__ float4             g_sboxes[MAXN];                // boxes in sorted order
__device__ float              g_sscores[MAXN];               // scores in sorted order
__device__ int                g_rank[MAXN];                  // sorted position of input i
__device__ unsigned long long g_keep[MAXCB];                 // keep bits per 64-chunk
__device__ int                g_prefix[MAXCB];               // kept-count prefix per chunk

// ---------------------------------------------------------------------------
// K0: zero the rank accumulators (graph replays reuse the static buffer)
// ---------------------------------------------------------------------------
__global__ void k_zero(int n) {
    int i = blockIdx.x * blockDim.x + threadIdx.x;
    if (i < n) g_rank[i] = 0;
}

// ---------------------------------------------------------------------------
// K1: stable descending rank via brute-force counting.
// rank[i] = #{ j : s_j > s_i  ||  (s_j == s_i && j < i) }
// ---------------------------------------------------------------------------
__global__ void k_count(const float* __restrict__ scores, int N, int segSize) {
    int i  = blockIdx.x * blockDim.x + threadIdx.x;
    int j0 = blockIdx.y * segSize;
    int j1 = min(j0 + segSize, N);
    __shared__ float sh[256];

    float si = (i < N) ? scores[i] : 0.0f;
    int cnt = 0;
    for (int jb = j0; jb < j1; jb += 256) {
        int j = jb + threadIdx.x;
        sh[threadIdx.x] = (j < j1) ? scores[j] : -1e30f;
        __syncthreads();
        int lim = min(256, j1 - jb);
        #pragma unroll 4
        for (int t = 0; t < lim; t++) {
            float sj = sh[t];
            int jg = jb + t;
            cnt += (sj > si) || (sj == si && jg < i);
        }
        __syncthreads();
    }
    if (i < N && cnt) atomicAdd(&g_rank[i], cnt);
}

// ---------------------------------------------------------------------------
// K1b: scatter inputs into sorted order
// ---------------------------------------------------------------------------
__global__ void k_scatter(const float4* __restrict__ boxes,
                          const float* __restrict__ scores, int N) {
    int i = blockIdx.x * blockDim.x + threadIdx.x;
    if (i >= N) return;
    int r = g_rank[i];
    g_sboxes[r]  = boxes[i];
    g_sscores[r] = scores[i];
}

// ---------------------------------------------------------------------------
// K2: pairwise IoU suppression bitmask (upper triangle of 64x64 blocks).
// Off-diagonal blocks: fully unrolled, no row/col compare (padding boxes are
// all-zero -> inter=0 -> never suppress). Diagonal blocks also write g_diag.
// ---------------------------------------------------------------------------
__global__ void k_mask(int N, int CB) {
    int cb = blockIdx.x, rb = blockIdx.y;
    if (cb < rb) return;
    __shared__ float4 cbox[64];
    int t  = threadIdx.x;
    int cg = cb * 64 + t;
    cbox[t] = (cg < N) ? g_sboxes[cg] : make_float4(0.f, 0.f, 0.f, 0.f);
    __syncthreads();

    int rg = rb * 64 + t;
    if (rg >= N) return;
    float4 r = g_sboxes[rg];
    float ra = (r.z - r.x) * (r.w - r.y);

    unsigned long long m = 0;
    if (cb > rb) {
        #pragma unroll
        for (int j = 0; j < 64; j++) {
            float4 c = cbox[j];
            float ix1 = fmaxf(r.x, c.x), iy1 = fmaxf(r.y, c.y);
            float ix2 = fminf(r.z, c.z), iy2 = fminf(r.w, c.w);
            float iw = fmaxf(ix2 - ix1, 0.0f), ih = fmaxf(iy2 - iy1, 0.0f);
            float inter = iw * ih;
            float ca = (c.z - c.x) * (c.w - c.y);
            float u  = fmaxf(ra + ca - inter, 1e-9f);
            if (inter > 0.5f * u) m |= 1ull << j;
        }
    } else {
        // diagonal block: only suppress later (lower-score) boxes j > t
        #pragma unroll
        for (int j = 0; j < 64; j++) {
            if (j <= t) continue;
            float4 c = cbox[j];
            float ix1 = fmaxf(r.x, c.x), iy1 = fmaxf(r.y, c.y);
            float ix2 = fminf(r.z, c.z), iy2 = fminf(r.w, c.w);
            float iw = fmaxf(ix2 - ix1, 0.0f), ih = fmaxf(iy2 - iy1, 0.0f);
            float inter = iw * ih;
            float ca = (c.z - c.x) * (c.w - c.y);
            float u  = fmaxf(ra + ca - inter, 1e-9f);
            if (inter > 0.5f * u) m |= 1ull << j;
        }
        g_diag[rg] = m;
    }
    g_mask[(size_t)rg * CB + cb] = m;
}

// ---------------------------------------------------------------------------
// K3: serial greedy scan with early termination at MAXP kept.
// Phase A (thread 0): ffs over pending bits (iterations = #kept in chunk).
// Phase B: one thread per future word; batched independent loads.
// Diag masks double-buffered in smem, prefetched by idle threads (tid>=192).
// ---------------------------------------------------------------------------
__global__ void k_scan(int N, int CB) {
    __shared__ unsigned long long removed[MAXCB];
    __shared__ unsigned long long diagbuf[2][64];
    __shared__ unsigned long long s_keepw;
    __shared__ int s_stop;
    int tid = threadIdx.x;

    for (int w = tid; w < CB; w += blockDim.x) removed[w] = 0ull;
    if (tid < 64) diagbuf[0][tid] = (tid < N) ? g_diag[tid] : 0ull;
    if (tid == 0) s_stop = 0;
    __syncthreads();

    int total = 0;   // meaningful on thread 0 only
    int cstop = CB;  // first chunk NOT fully needed (exclusive of processed)

    for (int c = 0; c < CB; c++) {
        const unsigned long long* d = diagbuf[c & 1];

        if (tid == 0) {
            unsigned long long rem = removed[c];
            int valid = N - c * 64;
            unsigned long long vmask =
                (valid >= 64) ? ~0ull : ((valid <= 0) ? 0ull : ((1ull << valid) - 1ull));
            unsigned long long pending = ~rem & vmask;
            unsigned long long kp = 0ull;
            while (pending) {
                int i = __ffsll((long long)pending) - 1;
                kp |= 1ull << i;
                pending &= ~d[i];
                pending &= pending - 1ull;  // clear bit i (lowest set)
            }
            g_keep[c]   = kp;
            g_prefix[c] = total;
            total += __popcll(kp);
            s_keepw = kp;
            if (total >= MAXP) s_stop = 1;
        }
        __syncthreads();

        if (s_stop) { cstop = c + 1; break; }
        unsigned long long kp = s_keepw;

        // phase B: propagate suppression of this chunk's kept boxes
        int w = c + 1 + tid;
        if (w < CB && kp) {
            const unsigned long long* mp = g_mask + w;
            long long cbase = (long long)c * 64;
            unsigned long long acc = removed[w];
            unsigned long long k = kp;
            while (k) {
                int i0 = __ffsll((long long)k) - 1; k &= k - 1ull;
                int i1 = -1, i2 = -1, i3 = -1;
                if (k) { i1 = __ffsll((long long)k) - 1; k &= k - 1ull; }
                if (k) { i2 = __ffsll((long long)k) - 1; k &= k - 1ull; }
                if (k) { i3 = __ffsll((long long)k) - 1; k &= k - 1ull; }
                unsigned long long a0 = mp[(cbase + i0) * CB];
                unsigned long long a1 = (i1 >= 0) ? mp[(cbase + i1) * CB] : 0ull;
                unsigned long long a2 = (i2 >= 0) ? mp[(cbase + i2) * CB] : 0ull;
                unsigned long long a3 = (i3 >= 0) ? mp[(cbase + i3) * CB] : 0ull;
                acc |= a0 | a1 | a2 | a3;
            }
            removed[w] = acc;
        }

        // prefetch next chunk's diagonal masks (threads 192..255 are never
        // used by phase B since CB <= 157)
        if (tid >= 192 && c + 1 < CB) {
            int g = (c + 1) * 64 + (tid - 192);
            diagbuf[(c + 1) & 1][tid - 192] = (g < N) ? g_diag[g] : 0ull;
        }
        __syncthreads();
    }

    // chunks after the stop point can never contribute kept outputs
    // (their rank >= MAXP); zero their keep words.
    for (int c2 = cstop + tid; c2 < CB; c2 += blockDim.x) g_keep[c2] = 0ull;
}

// ---------------------------------------------------------------------------
// K4: apply MAX_PROPOSALS cutoff and emit outputs:
//   out[0 : 4N) boxes | out[4N : 5N) scores | out[5N : 6N) keep as 0/1
// ---------------------------------------------------------------------------
__global__ void k_out(float* __restrict__ out, int N) {
    int p = blockIdx.x * blockDim.x + threadIdx.x;
    if (p >= N) return;
    int c = p >> 6, i = p & 63;
    unsigned long long kw = g_keep[c];
    bool kept = (kw >> i) & 1ull;
    int r = g_prefix[c] + __popcll(kw & ((1ull << i) - 1ull));
    bool fin = kept && (r < MAXP);

    float4 b = fin ? g_sboxes[p] : make_float4(0.f, 0.f, 0.f, 0.f);
    ((float4*)out)[p] = b;
    out[4 * N + p] = fin ? g_sscores[p] : 0.0f;
    out[5 * N + p] = fin ? 1.0f : 0.0f;
}

// ---------------------------------------------------------------------------
extern "C" void kernel_launch(void* const* d_in, const int* in_sizes, int n_in,
                              void* d_out, int out_size) {
    const float4* boxes  = (const float4*)d_in[0];
    const float*  scores = (const float*)d_in[1];
    int N  = in_sizes[1];
    int CB = (N + 63) / 64;

    k_zero<<<(N + 255) / 256, 256>>>(N);

    int segSize = (N + 7) / 8;
    dim3 g1((N + 255) / 256, 8);
    k_count<<<g1, 256>>>(scores, N, segSize);

    k_scatter<<<(N + 255) / 256, 256>>>(boxes, scores, N);

    dim3 g2(CB, CB);
    k_mask<<<g2, 64>>>(N, CB);

    k_scan<<<1, 256>>>(N, CB);

    k_out<<<(N + 255) / 256, 256>>>((float*)d_out, N);
}